// round 13
// baseline (speedup 1.0000x reference)
#include <cuda_runtime.h>
#include <cuda_bf16.h>

static constexpr int UN = 2048;
static constexpr int TN = 512;
static constexpr int QN = 10000;
static constexpr int HN = 128;

// Scratch (__device__ globals)
__device__ float4 g_trans[UN * TN];   // [t][u] : {lmda, lmda*mu, eps_ab, mask}
__device__ float2 g_AB[UN * TN];      // [t][u] : {A, B}
__device__ float  g_abT[UN * TN];     // [t][u] : ability (transposed)
__device__ float  g_muTab[2 * QN];
__device__ float  g_lmTab[2 * QN];
__device__ float  g_diffA[QN];
__device__ float  g_discA[QN];

__device__ __forceinline__ float gelu_exact(float x) {
    return 0.5f * x * (1.0f + erff(x * 0.70710678118654752f));
}

// ---------------------------------------------------------------------------
// Kernel 1: per-(question, resp) tables — 4 threads cooperate per row.
// Each thread holds 32 h1 values in registers (no spill); partial layer-2
// sums reduced across the 4 sub-threads with shfl_xor. 80k threads total.
// ---------------------------------------------------------------------------
__global__ void __launch_bounds__(128) k_tables(
    const float* __restrict__ diff_mu, const float* __restrict__ diff_lv,
    const float* __restrict__ disc_mu, const float* __restrict__ disc_lv,
    const float* __restrict__ eps_diff, const float* __restrict__ eps_disc,
    const float* __restrict__ W1, const float* __restrict__ b1,
    const float* __restrict__ W2, const float* __restrict__ b2,
    const float* __restrict__ W3, const float* __restrict__ b3)
{
    int tid = threadIdx.x;
    int q4  = tid & 3;                    // quarter index 0..3
    int rb  = tid >> 2;                   // row within block (0..31)
    int i   = blockIdx.x * 32 + rb;       // global (q, resp) row, 625*32 = 20000
    int q   = i >> 1;

    float dif = diff_mu[q] + expf(0.5f * diff_lv[q]) * eps_diff[q];
    float dis = disc_mu[q] + expf(0.5f * disc_lv[q]) * eps_disc[q];
    if (q4 == 0 && (i & 1) == 0) { g_diffA[q] = dif; g_discA[q] = dis; }
    float x2 = (float)(i & 1);

    // Layer 1: this thread's 32 hidden units j = q4*32 + jj
    float h1[32];
#pragma unroll
    for (int jj = 0; jj < 32; ++jj) {
        int j = q4 * 32 + jj;
        float v = fmaf(dif, __ldg(&W1[j]),
                  fmaf(dis, __ldg(&W1[HN + j]),
                  fmaf(x2,  __ldg(&W1[2 * HN + j]), __ldg(&b1[j]))));
        h1[jj] = gelu_exact(v);
    }

    // Layers 2+3: partial sums over this thread's k-range, shfl-reduced.
    float o0 = __ldg(&b3[0]);
    float o1 = __ldg(&b3[1]);
#pragma unroll 1
    for (int jg = 0; jg < HN; jg += 4) {
        float a0 = 0.f, a1 = 0.f, a2 = 0.f, a3 = 0.f;
#pragma unroll
        for (int kk = 0; kk < 32; ++kk) {
            int k = q4 * 32 + kk;
            float4 w = __ldg((const float4*)(W2 + k * HN + jg));
            a0 = fmaf(h1[kk], w.x, a0);
            a1 = fmaf(h1[kk], w.y, a1);
            a2 = fmaf(h1[kk], w.z, a2);
            a3 = fmaf(h1[kk], w.w, a3);
        }
        // reduce across the 4 sub-threads (lane bits 0-1)
        a0 += __shfl_xor_sync(0xffffffffu, a0, 1);
        a1 += __shfl_xor_sync(0xffffffffu, a1, 1);
        a2 += __shfl_xor_sync(0xffffffffu, a2, 1);
        a3 += __shfl_xor_sync(0xffffffffu, a3, 1);
        a0 += __shfl_xor_sync(0xffffffffu, a0, 2);
        a1 += __shfl_xor_sync(0xffffffffu, a1, 2);
        a2 += __shfl_xor_sync(0xffffffffu, a2, 2);
        a3 += __shfl_xor_sync(0xffffffffu, a3, 2);

        a0 = gelu_exact(a0 + __ldg(&b2[jg + 0]));
        a1 = gelu_exact(a1 + __ldg(&b2[jg + 1]));
        a2 = gelu_exact(a2 + __ldg(&b2[jg + 2]));
        a3 = gelu_exact(a3 + __ldg(&b2[jg + 3]));

        float4 wa = __ldg((const float4*)(W3 + jg * 2));
        float4 wb = __ldg((const float4*)(W3 + jg * 2 + 4));
        o0 = fmaf(a0, wa.x, o0);  o1 = fmaf(a0, wa.y, o1);
        o0 = fmaf(a1, wa.z, o0);  o1 = fmaf(a1, wa.w, o1);
        o0 = fmaf(a2, wb.x, o0);  o1 = fmaf(a2, wb.y, o1);
        o0 = fmaf(a3, wb.z, o0);  o1 = fmaf(a3, wb.w, o1);
    }
    if (q4 == 0) {
        g_muTab[i] = o0;
        g_lmTab[i] = fminf(expf(-o1), 1e32f);
    }
}

// ---------------------------------------------------------------------------
// Kernel 2: gather per-trial (lmda, lmda*mu, eps, mask), transpose to (T,U).
// ---------------------------------------------------------------------------
__global__ void k_gather(const int* __restrict__ mask, const int* __restrict__ q_id,
                         const float* __restrict__ resp, const float* __restrict__ eps_ab)
{
    __shared__ float4 tile[32][33];
    int t0 = blockIdx.x * 32, u0 = blockIdx.y * 32;
    int tx = threadIdx.x, ty = threadIdx.y;  // blockDim = (32, 8)
#pragma unroll
    for (int yy = 0; yy < 4; ++yy) {
        int u = u0 + ty + yy * 8;
        int t = t0 + tx;
        int gi = u * TN + t;
        int qq = __ldg(&q_id[gi]);
        float rv = __ldg(&resp[gi]);
        int idx = qq * 2 + (rv > 0.5f ? 1 : 0);
        float l = g_lmTab[idx];
        float lm = l * g_muTab[idx];
        tile[ty + yy * 8][tx] = make_float4(l, lm,
                                            __ldg(&eps_ab[gi]),
                                            __ldg(&mask[gi]) ? 1.0f : 0.0f);
    }
    __syncthreads();
#pragma unroll
    for (int yy = 0; yy < 4; ++yy) {
        int t = t0 + ty + yy * 8;
        int u = u0 + tx;
        g_trans[t * UN + u] = tile[tx][ty + yy * 8];
    }
}

// ---------------------------------------------------------------------------
// Kernel 3: fused backward + forward scan, one thread per user.
// ---------------------------------------------------------------------------
__global__ void k_scan()
{
    int u = blockIdx.x * blockDim.x + threadIdx.x;
    if (u >= UN) return;

    float a = 0.f, b = 0.f;
#pragma unroll 4
    for (int t = TN - 1; t >= 0; --t) {
        float4 v = g_trans[t * UN + u];
        g_AB[t * UN + u] = make_float2(a, b);
        float d  = v.x + a;
        float e  = d + 1.f;
        float an = __fdividef(d, e);
        float bn = __fdividef(fmaf(a, b, v.y), d);
        bool mk = v.w != 0.f;
        a = mk ? an : a;
        b = mk ? bn : b;
    }

    float ab = 0.f;
#pragma unroll 4
    for (int t = 0; t < TN; ++t) {
        float4 v = g_trans[t * UN + u];
        float2 p = g_AB[t * UN + u];
        float r2 = __fdividef(1.f, 1.f + v.x + p.x);
        float c0 = fmaf(p.x, p.y, v.y);
        float se = sqrtf(1.f - p.x) * v.z;
        float mu_t = (ab + c0) * r2;
        if (v.w != 0.f) ab = mu_t + se;
        g_abT[t * UN + u] = ab;
    }
}

// ---------------------------------------------------------------------------
// Kernel 4: transpose ability back to (U,T), compute logits, write output.
// ---------------------------------------------------------------------------
__global__ void k_out(const int* __restrict__ q_id, float* __restrict__ out)
{
    __shared__ float tile[32][33];
    int t0 = blockIdx.x * 32, u0 = blockIdx.y * 32;
    int tx = threadIdx.x, ty = threadIdx.y;  // (32, 8)
#pragma unroll
    for (int yy = 0; yy < 4; ++yy) {
        int t = t0 + ty + yy * 8;
        tile[tx][ty + yy * 8] = g_abT[t * UN + u0 + tx];
    }
    __syncthreads();
    float* logits = out;
    float* abil = out + UN * TN;
#pragma unroll
    for (int yy = 0; yy < 4; ++yy) {
        int u = u0 + ty + yy * 8;
        int t = t0 + tx;
        int gi = u * TN + t;
        float ab = tile[ty + yy * 8][tx];
        int qq = __ldg(&q_id[gi]);
        abil[gi] = ab;
        logits[gi] = g_discA[qq] * (ab - g_diffA[qq]);
    }
}

extern "C" void kernel_launch(void* const* d_in, const int* in_sizes, int n_in,
                              void* d_out, int out_size)
{
    const int*   mask     = (const int*)d_in[0];
    const int*   q_id     = (const int*)d_in[1];
    const float* resp     = (const float*)d_in[2];
    const float* diff_mu  = (const float*)d_in[3];
    const float* diff_lv  = (const float*)d_in[4];
    const float* disc_mu  = (const float*)d_in[5];
    const float* disc_lv  = (const float*)d_in[6];
    const float* W1       = (const float*)d_in[7];
    const float* b1       = (const float*)d_in[8];
    const float* W2       = (const float*)d_in[9];
    const float* b2       = (const float*)d_in[10];
    const float* W3       = (const float*)d_in[11];
    const float* b3       = (const float*)d_in[12];
    const float* eps_diff = (const float*)d_in[13];
    const float* eps_disc = (const float*)d_in[14];
    const float* eps_ab   = (const float*)d_in[15];
    float* out = (float*)d_out;

    // 625 blocks * 32 rows/block = 20000 rows, 4 threads per row
    k_tables<<<625, 128>>>(diff_mu, diff_lv, disc_mu, disc_lv,
                           eps_diff, eps_disc,
                           W1, b1, W2, b2, W3, b3);
    dim3 tb(32, 8);
    dim3 gb(TN / 32, UN / 32);
    k_gather<<<gb, tb>>>(mask, q_id, resp, eps_ab);
    k_scan<<<UN / 256, 256>>>();
    k_out<<<gb, tb>>>(q_id, out);
}

// round 14
// speedup vs baseline: 1.1716x; 1.1716x over previous
#include <cuda_runtime.h>
#include <cuda_bf16.h>

static constexpr int UN = 2048;
static constexpr int TN = 512;
static constexpr int QN = 10000;
static constexpr int HN = 128;

// Scratch (__device__ globals)
__device__ float4 g_trans[UN * TN];   // [t][u] : {lmda, lmda*mu, eps_ab, mask}
__device__ float2 g_AB[UN * TN];      // [t][u] : {A, B}
__device__ float  g_abT[UN * TN];     // [t][u] : ability (transposed)
__device__ float  g_muTab[2 * QN];
__device__ float  g_lmTab[2 * QN];
__device__ float  g_diffA[QN];
__device__ float  g_discA[QN];

__device__ __forceinline__ float gelu_exact(float x) {
    return 0.5f * x * (1.0f + erff(x * 0.70710678118654752f));
}

// ---------------------------------------------------------------------------
// Kernel 1: per-(question, resp) tables (monolithic R12 form — reverted).
// ---------------------------------------------------------------------------
__global__ void k_tables(const float* __restrict__ diff_mu, const float* __restrict__ diff_lv,
                         const float* __restrict__ disc_mu, const float* __restrict__ disc_lv,
                         const float* __restrict__ eps_diff, const float* __restrict__ eps_disc,
                         const float* __restrict__ W1, const float* __restrict__ b1,
                         const float* __restrict__ W2, const float* __restrict__ b2,
                         const float* __restrict__ W3, const float* __restrict__ b3)
{
    int i = blockIdx.x * blockDim.x + threadIdx.x;
    if (i >= 2 * QN) return;
    int q = i >> 1;
    float dif = diff_mu[q] + expf(0.5f * diff_lv[q]) * eps_diff[q];
    float dis = disc_mu[q] + expf(0.5f * disc_lv[q]) * eps_disc[q];
    if ((i & 1) == 0) { g_diffA[q] = dif; g_discA[q] = dis; }
    float x2 = (float)(i & 1);

    float h1[HN];
#pragma unroll
    for (int j = 0; j < HN; ++j) {
        float v = fmaf(dif, __ldg(&W1[j]),
                  fmaf(dis, __ldg(&W1[HN + j]),
                  fmaf(x2,  __ldg(&W1[2 * HN + j]), __ldg(&b1[j]))));
        h1[j] = gelu_exact(v);
    }

    float o0 = __ldg(&b3[0]);
    float o1 = __ldg(&b3[1]);
#pragma unroll 1
    for (int jg = 0; jg < HN; jg += 4) {
        float a0 = __ldg(&b2[jg + 0]);
        float a1 = __ldg(&b2[jg + 1]);
        float a2 = __ldg(&b2[jg + 2]);
        float a3 = __ldg(&b2[jg + 3]);
#pragma unroll
        for (int k = 0; k < HN; ++k) {
            float4 w = __ldg((const float4*)(W2 + k * HN + jg));
            a0 = fmaf(h1[k], w.x, a0);
            a1 = fmaf(h1[k], w.y, a1);
            a2 = fmaf(h1[k], w.z, a2);
            a3 = fmaf(h1[k], w.w, a3);
        }
        a0 = gelu_exact(a0);
        a1 = gelu_exact(a1);
        a2 = gelu_exact(a2);
        a3 = gelu_exact(a3);
        float4 wa = __ldg((const float4*)(W3 + jg * 2));
        float4 wb = __ldg((const float4*)(W3 + jg * 2 + 4));
        o0 = fmaf(a0, wa.x, o0);  o1 = fmaf(a0, wa.y, o1);
        o0 = fmaf(a1, wa.z, o0);  o1 = fmaf(a1, wa.w, o1);
        o0 = fmaf(a2, wb.x, o0);  o1 = fmaf(a2, wb.y, o1);
        o0 = fmaf(a3, wb.z, o0);  o1 = fmaf(a3, wb.w, o1);
    }
    g_muTab[i] = o0;
    g_lmTab[i] = fminf(expf(-o1), 1e32f);
}

// ---------------------------------------------------------------------------
// Kernel 2: gather per-trial (lmda, lmda*mu, eps, mask), transpose to (T,U).
// ---------------------------------------------------------------------------
__global__ void k_gather(const int* __restrict__ mask, const int* __restrict__ q_id,
                         const float* __restrict__ resp, const float* __restrict__ eps_ab)
{
    __shared__ float4 tile[32][33];
    int t0 = blockIdx.x * 32, u0 = blockIdx.y * 32;
    int tx = threadIdx.x, ty = threadIdx.y;  // blockDim = (32, 8)
#pragma unroll
    for (int yy = 0; yy < 4; ++yy) {
        int u = u0 + ty + yy * 8;
        int t = t0 + tx;
        int gi = u * TN + t;
        int qq = __ldg(&q_id[gi]);
        float rv = __ldg(&resp[gi]);
        int idx = qq * 2 + (rv > 0.5f ? 1 : 0);
        float l = g_lmTab[idx];
        float lm = l * g_muTab[idx];
        tile[ty + yy * 8][tx] = make_float4(l, lm,
                                            __ldg(&eps_ab[gi]),
                                            __ldg(&mask[gi]) ? 1.0f : 0.0f);
    }
    __syncthreads();
#pragma unroll
    for (int yy = 0; yy < 4; ++yy) {
        int t = t0 + ty + yy * 8;
        int u = u0 + tx;
        g_trans[t * UN + u] = tile[tx][ty + yy * 8];
    }
}

// ---------------------------------------------------------------------------
// Kernel 3: fused backward + forward scan, one thread per user.
// 32 blocks x 64 threads (4x more SMs than before) + unroll 8 so ptxas
// front-batches 8 carry-independent LDG.128s per body -> lat/8 per iter.
// ---------------------------------------------------------------------------
__global__ void __launch_bounds__(64) k_scan()
{
    int u = blockIdx.x * blockDim.x + threadIdx.x;
    if (u >= UN) return;

    float a = 0.f, b = 0.f;
#pragma unroll 8
    for (int t = TN - 1; t >= 0; --t) {
        float4 v = g_trans[t * UN + u];
        g_AB[t * UN + u] = make_float2(a, b);
        float d  = v.x + a;
        float e  = d + 1.f;
        float an = __fdividef(d, e);
        float bn = __fdividef(fmaf(a, b, v.y), d);
        bool mk = v.w != 0.f;
        a = mk ? an : a;
        b = mk ? bn : b;
    }

    float ab = 0.f;
#pragma unroll 8
    for (int t = 0; t < TN; ++t) {
        float4 v = g_trans[t * UN + u];
        float2 p = g_AB[t * UN + u];
        float r2 = __fdividef(1.f, 1.f + v.x + p.x);
        float c0 = fmaf(p.x, p.y, v.y);
        float se = sqrtf(1.f - p.x) * v.z;
        float mu_t = (ab + c0) * r2;
        if (v.w != 0.f) ab = mu_t + se;
        g_abT[t * UN + u] = ab;
    }
}

// ---------------------------------------------------------------------------
// Kernel 4: transpose ability back to (U,T), compute logits, write output.
// ---------------------------------------------------------------------------
__global__ void k_out(const int* __restrict__ q_id, float* __restrict__ out)
{
    __shared__ float tile[32][33];
    int t0 = blockIdx.x * 32, u0 = blockIdx.y * 32;
    int tx = threadIdx.x, ty = threadIdx.y;  // (32, 8)
#pragma unroll
    for (int yy = 0; yy < 4; ++yy) {
        int t = t0 + ty + yy * 8;
        tile[tx][ty + yy * 8] = g_abT[t * UN + u0 + tx];
    }
    __syncthreads();
    float* logits = out;
    float* abil = out + UN * TN;
#pragma unroll
    for (int yy = 0; yy < 4; ++yy) {
        int u = u0 + ty + yy * 8;
        int t = t0 + tx;
        int gi = u * TN + t;
        float ab = tile[ty + yy * 8][tx];
        int qq = __ldg(&q_id[gi]);
        abil[gi] = ab;
        logits[gi] = g_discA[qq] * (ab - g_diffA[qq]);
    }
}

extern "C" void kernel_launch(void* const* d_in, const int* in_sizes, int n_in,
                              void* d_out, int out_size)
{
    const int*   mask     = (const int*)d_in[0];
    const int*   q_id     = (const int*)d_in[1];
    const float* resp     = (const float*)d_in[2];
    const float* diff_mu  = (const float*)d_in[3];
    const float* diff_lv  = (const float*)d_in[4];
    const float* disc_mu  = (const float*)d_in[5];
    const float* disc_lv  = (const float*)d_in[6];
    const float* W1       = (const float*)d_in[7];
    const float* b1       = (const float*)d_in[8];
    const float* W2       = (const float*)d_in[9];
    const float* b2       = (const float*)d_in[10];
    const float* W3       = (const float*)d_in[11];
    const float* b3       = (const float*)d_in[12];
    const float* eps_diff = (const float*)d_in[13];
    const float* eps_disc = (const float*)d_in[14];
    const float* eps_ab   = (const float*)d_in[15];
    float* out = (float*)d_out;

    k_tables<<<(2 * QN + 127) / 128, 128>>>(diff_mu, diff_lv, disc_mu, disc_lv,
                                            eps_diff, eps_disc,
                                            W1, b1, W2, b2, W3, b3);
    dim3 tb(32, 8);
    dim3 gb(TN / 32, UN / 32);
    k_gather<<<gb, tb>>>(mask, q_id, resp, eps_ab);
    k_scan<<<UN / 64, 64>>>();
    k_out<<<gb, tb>>>(q_id, out);
}

// round 17
// speedup vs baseline: 1.6301x; 1.3913x over previous
#include <cuda_runtime.h>
#include <cuda_bf16.h>

static constexpr int UN = 2048;
static constexpr int TN = 512;
static constexpr int QN = 10000;
static constexpr int HN = 128;

// Scratch (__device__ globals)
__device__ float4 g_trans[UN * TN];   // [t][u] : {lmda, lmda*mu, eps_ab, mask}
__device__ float2 g_AB[UN * TN];      // [t][u] : {A, B}
__device__ float  g_abT[UN * TN];     // [t][u] : ability (transposed)
__device__ float  g_muTab[2 * QN];
__device__ float  g_lmTab[2 * QN];
__device__ float  g_diffA[QN];
__device__ float  g_discA[QN];

__device__ __forceinline__ float gelu_exact(float x) {
    return 0.5f * x * (1.0f + erff(x * 0.70710678118654752f));
}

// Dynamic smem layout (floats)
static constexpr int W2OFF = 0;                 // 16384
static constexpr int W1OFF = 16384;             // 384
static constexpr int B1OFF = W1OFF + 384;       // 128
static constexpr int B2OFF = B1OFF + 128;       // 128
static constexpr int W3OFF = B2OFF + 128;       // 256
static constexpr int B3OFF = W3OFF + 256;       // 2
static constexpr int H1OFF = B3OFF + 4;         // 8 warps * 4 rows * 128
static constexpr int SMEM_FLOATS = H1OFF + 8 * 4 * 128;
static constexpr int SMEM_BYTES  = SMEM_FLOATS * 4;   // ~85.6 KB

// ---------------------------------------------------------------------------
// Kernel 1: warp-cooperative tables. One warp handles 4 (q,resp) rows.
// Lanes own 4 output columns each; k-loop is whole per lane (no mid-loop
// shuffles). All weights + h1 in shared memory; ~60 regs, no spills.
// 625 blocks x 256 threads = 5000 warps = 20000 rows.
// ---------------------------------------------------------------------------
__global__ void __launch_bounds__(256) k_tables(
    const float* __restrict__ diff_mu, const float* __restrict__ diff_lv,
    const float* __restrict__ disc_mu, const float* __restrict__ disc_lv,
    const float* __restrict__ eps_diff, const float* __restrict__ eps_disc,
    const float* __restrict__ W1, const float* __restrict__ b1,
    const float* __restrict__ W2, const float* __restrict__ b2,
    const float* __restrict__ W3, const float* __restrict__ b3)
{
    extern __shared__ float sm[];
    int tid  = threadIdx.x;
    int wid  = tid >> 5;
    int lane = tid & 31;

    // Cooperative load of all weights into smem
    {
        const float4* src = (const float4*)W2;
        float4* dst = (float4*)(sm + W2OFF);
#pragma unroll
        for (int it = 0; it < 16; ++it) dst[it * 256 + tid] = src[it * 256 + tid];
        if (tid < 96)  ((float4*)(sm + W1OFF))[tid] = ((const float4*)W1)[tid];
        if (tid < 32)  ((float4*)(sm + B1OFF))[tid] = ((const float4*)b1)[tid];
        if (tid < 32)  ((float4*)(sm + B2OFF))[tid] = ((const float4*)b2)[tid];
        if (tid < 64)  ((float4*)(sm + W3OFF))[tid] = ((const float4*)W3)[tid];
        if (tid < 2)   sm[B3OFF + tid] = b3[tid];
    }
    __syncthreads();

    int gw = blockIdx.x * 8 + wid;     // global warp id, 0..4999
    int i0 = gw * 4;                   // first of 4 rows

    float* h1w = sm + H1OFF + wid * 512;   // [4][128]

    // Layer 1 for the 4 rows
#pragma unroll
    for (int r = 0; r < 4; ++r) {
        int i = i0 + r;
        int q = i >> 1;
        float dif = diff_mu[q] + expf(0.5f * diff_lv[q]) * eps_diff[q];
        float dis = disc_mu[q] + expf(0.5f * disc_lv[q]) * eps_disc[q];
        if (lane == 0 && (i & 1) == 0) { g_diffA[q] = dif; g_discA[q] = dis; }
        float x2 = (float)(i & 1);
#pragma unroll
        for (int m = 0; m < 4; ++m) {
            int j = lane + 32 * m;
            float v = fmaf(dif, sm[W1OFF + j],
                      fmaf(dis, sm[W1OFF + 128 + j],
                      fmaf(x2,  sm[W1OFF + 256 + j], sm[B1OFF + j])));
            h1w[r * 128 + j] = gelu_exact(v);
        }
    }
    __syncwarp();

    // Layer 2: lane owns columns j0..j0+3; full k-sum per lane (no shuffles)
    int j0 = lane * 4;
    float acc[4][4];
#pragma unroll
    for (int r = 0; r < 4; ++r)
#pragma unroll
        for (int c = 0; c < 4; ++c) acc[r][c] = 0.f;

#pragma unroll 4
    for (int k = 0; k < HN; ++k) {
        float4 w = *(const float4*)(sm + W2OFF + k * 128 + j0);
        float h0 = h1w[0 * 128 + k];
        float h1v = h1w[1 * 128 + k];
        float h2 = h1w[2 * 128 + k];
        float h3 = h1w[3 * 128 + k];
        acc[0][0] = fmaf(h0, w.x, acc[0][0]);
        acc[0][1] = fmaf(h0, w.y, acc[0][1]);
        acc[0][2] = fmaf(h0, w.z, acc[0][2]);
        acc[0][3] = fmaf(h0, w.w, acc[0][3]);
        acc[1][0] = fmaf(h1v, w.x, acc[1][0]);
        acc[1][1] = fmaf(h1v, w.y, acc[1][1]);
        acc[1][2] = fmaf(h1v, w.z, acc[1][2]);
        acc[1][3] = fmaf(h1v, w.w, acc[1][3]);
        acc[2][0] = fmaf(h2, w.x, acc[2][0]);
        acc[2][1] = fmaf(h2, w.y, acc[2][1]);
        acc[2][2] = fmaf(h2, w.z, acc[2][2]);
        acc[2][3] = fmaf(h2, w.w, acc[2][3]);
        acc[3][0] = fmaf(h3, w.x, acc[3][0]);
        acc[3][1] = fmaf(h3, w.y, acc[3][1]);
        acc[3][2] = fmaf(h3, w.z, acc[3][2]);
        acc[3][3] = fmaf(h3, w.w, acc[3][3]);
    }

    // Layer 3 partials + warp reduce
    float o0[4] = {0.f, 0.f, 0.f, 0.f};
    float o1[4] = {0.f, 0.f, 0.f, 0.f};
#pragma unroll
    for (int c = 0; c < 4; ++c) {
        int j = j0 + c;
        float bb = sm[B2OFF + j];
        float w30 = sm[W3OFF + j * 2];
        float w31 = sm[W3OFF + j * 2 + 1];
#pragma unroll
        for (int r = 0; r < 4; ++r) {
            float a = gelu_exact(acc[r][c] + bb);
            o0[r] = fmaf(a, w30, o0[r]);
            o1[r] = fmaf(a, w31, o1[r]);
        }
    }
#pragma unroll
    for (int off = 16; off > 0; off >>= 1) {
#pragma unroll
        for (int r = 0; r < 4; ++r) {
            o0[r] += __shfl_xor_sync(0xffffffffu, o0[r], off);
            o1[r] += __shfl_xor_sync(0xffffffffu, o1[r], off);
        }
    }
    if (lane == 0) {
        float b30 = sm[B3OFF], b31 = sm[B3OFF + 1];
#pragma unroll
        for (int r = 0; r < 4; ++r) {
            int i = i0 + r;
            g_muTab[i] = o0[r] + b30;
            g_lmTab[i] = fminf(expf(-(o1[r] + b31)), 1e32f);
        }
    }
}

// ---------------------------------------------------------------------------
// Kernel 2: gather per-trial (lmda, lmda*mu, eps, mask), transpose to (T,U).
// ---------------------------------------------------------------------------
__global__ void k_gather(const int* __restrict__ mask, const int* __restrict__ q_id,
                         const float* __restrict__ resp, const float* __restrict__ eps_ab)
{
    __shared__ float4 tile[32][33];
    int t0 = blockIdx.x * 32, u0 = blockIdx.y * 32;
    int tx = threadIdx.x, ty = threadIdx.y;  // blockDim = (32, 8)
#pragma unroll
    for (int yy = 0; yy < 4; ++yy) {
        int u = u0 + ty + yy * 8;
        int t = t0 + tx;
        int gi = u * TN + t;
        int qq = __ldg(&q_id[gi]);
        float rv = __ldg(&resp[gi]);
        int idx = qq * 2 + (rv > 0.5f ? 1 : 0);
        float l = g_lmTab[idx];
        float lm = l * g_muTab[idx];
        tile[ty + yy * 8][tx] = make_float4(l, lm,
                                            __ldg(&eps_ab[gi]),
                                            __ldg(&mask[gi]) ? 1.0f : 0.0f);
    }
    __syncthreads();
#pragma unroll
    for (int yy = 0; yy < 4; ++yy) {
        int t = t0 + ty + yy * 8;
        int u = u0 + tx;
        g_trans[t * UN + u] = tile[tx][ty + yy * 8];
    }
}

// ---------------------------------------------------------------------------
// Kernel 3: fused backward + forward scan (R14 config: 32 blocks x 64 thr).
// ---------------------------------------------------------------------------
__global__ void __launch_bounds__(64) k_scan()
{
    int u = blockIdx.x * blockDim.x + threadIdx.x;
    if (u >= UN) return;

    float a = 0.f, b = 0.f;
#pragma unroll 8
    for (int t = TN - 1; t >= 0; --t) {
        float4 v = g_trans[t * UN + u];
        g_AB[t * UN + u] = make_float2(a, b);
        float d  = v.x + a;
        float e  = d + 1.f;
        float an = __fdividef(d, e);
        float bn = __fdividef(fmaf(a, b, v.y), d);
        bool mk = v.w != 0.f;
        a = mk ? an : a;
        b = mk ? bn : b;
    }

    float ab = 0.f;
#pragma unroll 8
    for (int t = 0; t < TN; ++t) {
        float4 v = g_trans[t * UN + u];
        float2 p = g_AB[t * UN + u];
        float r2 = __fdividef(1.f, 1.f + v.x + p.x);
        float c0 = fmaf(p.x, p.y, v.y);
        float se = sqrtf(1.f - p.x) * v.z;
        float mu_t = (ab + c0) * r2;
        if (v.w != 0.f) ab = mu_t + se;
        g_abT[t * UN + u] = ab;
    }
}

// ---------------------------------------------------------------------------
// Kernel 4: transpose ability back to (U,T), compute logits, write output.
// ---------------------------------------------------------------------------
__global__ void k_out(const int* __restrict__ q_id, float* __restrict__ out)
{
    __shared__ float tile[32][33];
    int t0 = blockIdx.x * 32, u0 = blockIdx.y * 32;
    int tx = threadIdx.x, ty = threadIdx.y;  // (32, 8)
#pragma unroll
    for (int yy = 0; yy < 4; ++yy) {
        int t = t0 + ty + yy * 8;
        tile[tx][ty + yy * 8] = g_abT[t * UN + u0 + tx];
    }
    __syncthreads();
    float* logits = out;
    float* abil = out + UN * TN;
#pragma unroll
    for (int yy = 0; yy < 4; ++yy) {
        int u = u0 + ty + yy * 8;
        int t = t0 + tx;
        int gi = u * TN + t;
        float ab = tile[ty + yy * 8][tx];
        int qq = __ldg(&q_id[gi]);
        abil[gi] = ab;
        logits[gi] = g_discA[qq] * (ab - g_diffA[qq]);
    }
}

extern "C" void kernel_launch(void* const* d_in, const int* in_sizes, int n_in,
                              void* d_out, int out_size)
{
    const int*   mask     = (const int*)d_in[0];
    const int*   q_id     = (const int*)d_in[1];
    const float* resp     = (const float*)d_in[2];
    const float* diff_mu  = (const float*)d_in[3];
    const float* diff_lv  = (const float*)d_in[4];
    const float* disc_mu  = (const float*)d_in[5];
    const float* disc_lv  = (const float*)d_in[6];
    const float* W1       = (const float*)d_in[7];
    const float* b1       = (const float*)d_in[8];
    const float* W2       = (const float*)d_in[9];
    const float* b2       = (const float*)d_in[10];
    const float* W3       = (const float*)d_in[11];
    const float* b3       = (const float*)d_in[12];
    const float* eps_diff = (const float*)d_in[13];
    const float* eps_disc = (const float*)d_in[14];
    const float* eps_ab   = (const float*)d_in[15];
    float* out = (float*)d_out;

    // Idempotent, host-side, capture-legal; called every time (no static guard).
    cudaFuncSetAttribute(k_tables, cudaFuncAttributeMaxDynamicSharedMemorySize,
                         SMEM_BYTES);

    k_tables<<<625, 256, SMEM_BYTES>>>(diff_mu, diff_lv, disc_mu, disc_lv,
                                       eps_diff, eps_disc,
                                       W1, b1, W2, b2, W3, b3);
    dim3 tb(32, 8);
    dim3 gb(TN / 32, UN / 32);
    k_gather<<<gb, tb>>>(mask, q_id, resp, eps_ab);
    k_scan<<<UN / 64, 64>>>();
    k_out<<<gb, tb>>>(q_id, out);
}